// round 3
// baseline (speedup 1.0000x reference)
#include <cuda_runtime.h>

#define HH 128
#define WW 128
#define HWN 16384
#define BN 4
#define CN 64

typedef unsigned long long ull;

__device__ __constant__ int c_RATES[4] = {2, 3, 5, 9};

// Scratch (static device globals: allocation-free, graph-capturable)
__device__ float g_xhwc[BN * HWN * CN];            // [b][p][c]
__device__ float g_off[4][BN * HWN * 18];          // [j][b][p][k2]
__device__ float g_dwt[4 * 9 * 64 * 64];           // [i][k][c][o]
__device__ float g_cat[4 * BN * CN * HWN];         // [i][b][o][p]
__device__ float g_bsums[4 * BN * 64 * 64];        // [i][b][rowpair][o]
__device__ float g_gate[BN * 256];                 // 1 + sigmoid(...)

__device__ __forceinline__ ull pack2(float a, float b) {
    ull r;
    asm("mov.b64 %0, {%1, %2};" : "=l"(r) : "f"(a), "f"(b));
    return r;
}
__device__ __forceinline__ void ffma2(ull& d, ull a, ull b) {
    asm("fma.rn.f32x2 %0, %1, %2, %0;" : "+l"(d) : "l"(a), "l"(b));
}

// ---------------- K1: NCHW -> NHWC transpose of x ----------------
__global__ void transpose_kernel(const float* __restrict__ x) {
    __shared__ float tile[32][33];
    int b  = blockIdx.z;
    int p0 = blockIdx.x * 32;
    int c0 = blockIdx.y * 32;
    for (int i = threadIdx.y; i < 32; i += 8)
        tile[i][threadIdx.x] = x[(b * 64 + c0 + i) * HWN + p0 + threadIdx.x];
    __syncthreads();
    for (int i = threadIdx.y; i < 32; i += 8)
        g_xhwc[(b * HWN + p0 + i) * 64 + c0 + threadIdx.x] = tile[threadIdx.x][i];
}

// ---------------- K1b: dw (i,o,c,3,3) -> g_dwt [i][k][c][o] ----------------
__global__ void dwt_kernel(const float* __restrict__ dw) {
    int idx = blockIdx.x * 256 + threadIdx.x;  // < 147456
    int i  = idx / 36864;
    int r  = idx % 36864;
    int k  = r / 4096;
    int r2 = r & 4095;
    int c  = r2 >> 6;
    int o  = r2 & 63;
    g_dwt[idx] = dw[((i * 64 + o) * 64 + c) * 9 + k];
}

// ---------------- K2: offset conv (64 -> 18, dilated 3x3, relu), f32x2 ----------------
__global__ __launch_bounds__(256) void offset_kernel(const float* __restrict__ x,
                                                     const float* __restrict__ ow,
                                                     const float* __restrict__ ob) {
    __shared__ float ow_sh[9 * 64 * 20];
    int j = blockIdx.z, b = blockIdx.y;
    int rate = c_RATES[j];
    int tid = threadIdx.x;
    for (int idx = tid; idx < 9 * 64 * 20; idx += 256) {
        int k2 = idx % 20;
        int rest = idx / 20;
        int c = rest % 64;
        int t = rest / 64;
        ow_sh[idx] = (k2 < 18) ? ow[((j * 18 + k2) * 64 + c) * 9 + t] : 0.f;
    }
    __syncthreads();

    int p = blockIdx.x * 256 + tid;
    int y = p >> 7, xx = p & 127;
    ull acc2[10];
#pragma unroll
    for (int q = 0; q < 9; q++) acc2[q] = pack2(ob[j * 18 + 2 * q], ob[j * 18 + 2 * q + 1]);
    acc2[9] = 0ull;

    const float* xb = x + b * 64 * HWN;
    for (int t = 0; t < 9; t++) {
        int tyv = y + (t / 3 - 1) * rate;
        int txv = xx + (t % 3 - 1) * rate;
        if ((unsigned)tyv >= HH || (unsigned)txv >= WW) continue;
        const float* xp = xb + tyv * WW + txv;
#pragma unroll 4
        for (int c = 0; c < 64; c++) {
            float xc = xp[c * HWN];  // coalesced across warp
            ull xcc = pack2(xc, xc);
            const ull* wr = (const ull*)&ow_sh[(t * 64 + c) * 20];  // broadcast
#pragma unroll
            for (int q = 0; q < 10; q++) ffma2(acc2[q], wr[q], xcc);
        }
    }
    float* og = &g_off[j][(b * HWN + p) * 18];
#pragma unroll
    for (int q = 0; q < 9; q++) {
        float2 v = *(float2*)&acc2[q];
        og[2 * q]     = fmaxf(v.x, 0.f);
        og[2 * q + 1] = fmaxf(v.y, 0.f);
    }
}

// ---------------- K3: deform sample + GEMM per branch ----------------
// block = 2 image rows (256 px) x 64 outputs, 256 threads, 8x8 tile, f32x2
#define SPITCH 264
__global__ __launch_bounds__(256, 2) void branch_kernel() {
    extern __shared__ float smem[];
    float* A_sh = smem;                   // 64*64   = 4096 floats
    float* S_sh = smem + 4096;            // 64*264  = 16896 floats
    float* offs = smem + 4096 + 16896;    // 256*18  = 4608 floats

    int i = blockIdx.z, b = blockIdx.y, rp = blockIdx.x;  // rp = row pair
    int p0 = rp * 256;
    int j = (i + 3) & 3;
    int rate = c_RATES[i];
    int tid = threadIdx.x;
    int tx = tid & 31, ty = tid >> 5;

    const float* offg = &g_off[j][(b * HWN + p0) * 18];
    for (int idx = tid; idx < 256 * 18; idx += 256) offs[idx] = offg[idx];

    ull acc[8][4];
#pragma unroll
    for (int oy = 0; oy < 8; oy++)
#pragma unroll
        for (int q = 0; q < 4; q++) acc[oy][q] = 0ull;

    const float* xb  = &g_xhwc[b * HWN * 64];
    const float* dwt = &g_dwt[i * 9 * 4096];

    int myY = rp * 2 + (tid >> 7);   // this thread's gather pixel
    int myX = tid & 127;

    for (int k = 0; k < 9; k++) {
        __syncthreads();
        // stage A (dw k-chunk): 4096 floats, 16 per thread
        {
            const float4* src = (const float4*)(dwt + k * 4096);
            float4* dst = (float4*)A_sh;
#pragma unroll
            for (int u = 0; u < 4; u++) dst[tid + u * 256] = src[tid + u * 256];
        }
        // gather: this thread samples pixel tid for all 64 channels (8 per pass)
        {
            int kyr = (k / 3 - 1) * rate;
            int kxr = (k % 3 - 1) * rate;
            float dy = offs[tid * 18 + 2 * k];
            float dx = offs[tid * 18 + 2 * k + 1];
            float py = (float)(myY + kyr) + dy;
            float px = (float)(myX + kxr) + dx;
            float fy = floorf(py), fx = floorf(px);
            int iy0 = (int)fy, ix0 = (int)fx;
            float wy1 = py - fy, wx1 = px - fx;
            float wy0 = 1.f - wy1, wx0 = 1.f - wx1;
            bool vy0 = (unsigned)iy0 < HH;
            bool vy1 = (unsigned)(iy0 + 1) < HH;
            bool vx0 = (unsigned)ix0 < WW;
            bool vx1 = (unsigned)(ix0 + 1) < WW;
            float w00 = (vy0 && vx0) ? wy0 * wx0 : 0.f;
            float w01 = (vy0 && vx1) ? wy0 * wx1 : 0.f;
            float w10 = (vy1 && vx0) ? wy1 * wx0 : 0.f;
            float w11 = (vy1 && vx1) ? wy1 * wx1 : 0.f;
            ull w00d = pack2(w00, w00), w01d = pack2(w01, w01);
            ull w10d = pack2(w10, w10), w11d = pack2(w11, w11);
            int cy0 = min(max(iy0, 0), HH - 1), cy1 = min(max(iy0 + 1, 0), HH - 1);
            int cx0 = min(max(ix0, 0), WW - 1), cx1 = min(max(ix0 + 1, 0), WW - 1);
            const float* b00 = xb + (cy0 * WW + cx0) * 64;
            const float* b01 = xb + (cy0 * WW + cx1) * 64;
            const float* b10 = xb + (cy1 * WW + cx0) * 64;
            const float* b11 = xb + (cy1 * WW + cx1) * 64;
#pragma unroll
            for (int pass = 0; pass < 8; pass++) {
                int c0 = pass * 8;
                ulonglong2 t00 = *(const ulonglong2*)(b00 + c0);
                ulonglong2 t00b = *(const ulonglong2*)(b00 + c0 + 4);
                ulonglong2 t01 = *(const ulonglong2*)(b01 + c0);
                ulonglong2 t01b = *(const ulonglong2*)(b01 + c0 + 4);
                ulonglong2 t10 = *(const ulonglong2*)(b10 + c0);
                ulonglong2 t10b = *(const ulonglong2*)(b10 + c0 + 4);
                ulonglong2 t11 = *(const ulonglong2*)(b11 + c0);
                ulonglong2 t11b = *(const ulonglong2*)(b11 + c0 + 4);
                ull r0 = 0, r1 = 0, r2 = 0, r3 = 0;
                ffma2(r0, w00d, t00.x); ffma2(r1, w00d, t00.y); ffma2(r2, w00d, t00b.x); ffma2(r3, w00d, t00b.y);
                ffma2(r0, w01d, t01.x); ffma2(r1, w01d, t01.y); ffma2(r2, w01d, t01b.x); ffma2(r3, w01d, t01b.y);
                ffma2(r0, w10d, t10.x); ffma2(r1, w10d, t10.y); ffma2(r2, w10d, t10b.x); ffma2(r3, w10d, t10b.y);
                ffma2(r0, w11d, t11.x); ffma2(r1, w11d, t11.y); ffma2(r2, w11d, t11b.x); ffma2(r3, w11d, t11b.y);
                float2 f0 = *(float2*)&r0, f1 = *(float2*)&r1;
                float2 f2 = *(float2*)&r2, f3 = *(float2*)&r3;
                float* d = &S_sh[c0 * SPITCH + tid];  // lane = pixel: conflict-free
                d[0]          = f0.x;
                d[SPITCH]     = f0.y;
                d[2 * SPITCH] = f1.x;
                d[3 * SPITCH] = f1.y;
                d[4 * SPITCH] = f2.x;
                d[5 * SPITCH] = f2.y;
                d[6 * SPITCH] = f3.x;
                d[7 * SPITCH] = f3.y;
            }
        }
        __syncthreads();
        // GEMM: acc[oy][pp] += dup(A[c][ty*8+oy]) * S pixel-pairs
#pragma unroll 4
        for (int c = 0; c < 64; c++) {
            float4 a0 = *(const float4*)&A_sh[c * 64 + ty * 8];       // warp-uniform
            float4 a1 = *(const float4*)&A_sh[c * 64 + ty * 8 + 4];
            ulonglong2 B0 = *(const ulonglong2*)&S_sh[c * SPITCH + tx * 4];
            ulonglong2 B1 = *(const ulonglong2*)&S_sh[c * SPITCH + 128 + tx * 4];
            ull aa;
            aa = pack2(a0.x, a0.x); ffma2(acc[0][0], aa, B0.x); ffma2(acc[0][1], aa, B0.y); ffma2(acc[0][2], aa, B1.x); ffma2(acc[0][3], aa, B1.y);
            aa = pack2(a0.y, a0.y); ffma2(acc[1][0], aa, B0.x); ffma2(acc[1][1], aa, B0.y); ffma2(acc[1][2], aa, B1.x); ffma2(acc[1][3], aa, B1.y);
            aa = pack2(a0.z, a0.z); ffma2(acc[2][0], aa, B0.x); ffma2(acc[2][1], aa, B0.y); ffma2(acc[2][2], aa, B1.x); ffma2(acc[2][3], aa, B1.y);
            aa = pack2(a0.w, a0.w); ffma2(acc[3][0], aa, B0.x); ffma2(acc[3][1], aa, B0.y); ffma2(acc[3][2], aa, B1.x); ffma2(acc[3][3], aa, B1.y);
            aa = pack2(a1.x, a1.x); ffma2(acc[4][0], aa, B0.x); ffma2(acc[4][1], aa, B0.y); ffma2(acc[4][2], aa, B1.x); ffma2(acc[4][3], aa, B1.y);
            aa = pack2(a1.y, a1.y); ffma2(acc[5][0], aa, B0.x); ffma2(acc[5][1], aa, B0.y); ffma2(acc[5][2], aa, B1.x); ffma2(acc[5][3], aa, B1.y);
            aa = pack2(a1.z, a1.z); ffma2(acc[6][0], aa, B0.x); ffma2(acc[6][1], aa, B0.y); ffma2(acc[6][2], aa, B1.x); ffma2(acc[6][3], aa, B1.y);
            aa = pack2(a1.w, a1.w); ffma2(acc[7][0], aa, B0.x); ffma2(acc[7][1], aa, B0.y); ffma2(acc[7][2], aa, B1.x); ffma2(acc[7][3], aa, B1.y);
        }
    }

    // write outputs + per-rowpair channel sums (each o lives in exactly one warp)
    float* outp = &g_cat[((i * 4 + b) * 64) * HWN];
#pragma unroll
    for (int oy = 0; oy < 8; oy++) {
        int o = ty * 8 + oy;
        float2 p0v = *(float2*)&acc[oy][0];
        float2 p1v = *(float2*)&acc[oy][1];
        float2 p2v = *(float2*)&acc[oy][2];
        float2 p3v = *(float2*)&acc[oy][3];
        *(float4*)&outp[o * HWN + p0 + tx * 4]       = make_float4(p0v.x, p0v.y, p1v.x, p1v.y);
        *(float4*)&outp[o * HWN + p0 + 128 + tx * 4] = make_float4(p2v.x, p2v.y, p3v.x, p3v.y);
        float s = p0v.x + p0v.y + p1v.x + p1v.y + p2v.x + p2v.y + p3v.x + p3v.y;
        s += __shfl_xor_sync(0xffffffff, s, 1);
        s += __shfl_xor_sync(0xffffffff, s, 2);
        s += __shfl_xor_sync(0xffffffff, s, 4);
        s += __shfl_xor_sync(0xffffffff, s, 8);
        s += __shfl_xor_sync(0xffffffff, s, 16);
        if (tx == 0) g_bsums[((i * 4 + b) * 64 + rp) * 64 + o] = s;
    }
}

// ---------------- K4: SE MLP (tiny, one block) ----------------
__global__ void se_kernel(const float* __restrict__ w1, const float* __restrict__ b1,
                          const float* __restrict__ w2, const float* __restrict__ b2) {
    __shared__ float gm[4 * 256];
    __shared__ float h1[4 * 64];
    int tid = threadIdx.x;  // 256
    for (int idx = tid; idx < 1024; idx += 256) {
        int b = idx >> 8, ch = idx & 255;
        int i = ch >> 6, o = ch & 63;
        float s = 0.f;
        for (int r = 0; r < 64; r++)
            s += g_bsums[((i * 4 + b) * 64 + r) * 64 + o];
        gm[b * 256 + ch] = s * (1.f / 16384.f);
    }
    __syncthreads();
    {
        int b = tid >> 6, oc = tid & 63;
        float a = b1[oc];
        for (int ch = 0; ch < 256; ch++) a += w1[oc * 256 + ch] * gm[b * 256 + ch];
        h1[b * 64 + oc] = fmaxf(a, 0.f);
    }
    __syncthreads();
    for (int idx = tid; idx < 1024; idx += 256) {
        int b = idx >> 8, ch = idx & 255;
        float a = b2[ch];
        for (int oc = 0; oc < 64; oc++) a += w2[ch * 64 + oc] * h1[b * 64 + oc];
        g_gate[b * 256 + ch] = 1.f + 1.f / (1.f + expf(-a));
    }
}

// ---------------- K5: gated fuse + residual ----------------
__global__ void final_kernel(const float* __restrict__ x, float* __restrict__ out) {
    int idx = blockIdx.x * 256 + threadIdx.x;  // < 1048576 float4s
    int p4 = idx & 4095;
    int o  = (idx >> 12) & 63;
    int b  = idx >> 18;
    float4 a = ((const float4*)x)[idx];
#pragma unroll
    for (int i = 0; i < 4; i++) {
        float g = g_gate[b * 256 + i * 64 + o];
        float4 cv = ((const float4*)g_cat)[((i * 4 + b) * 64 + o) * 4096 + p4];
        a.x += g * cv.x;
        a.y += g * cv.y;
        a.z += g * cv.z;
        a.w += g * cv.w;
    }
    ((float4*)out)[idx] = a;
}

extern "C" void kernel_launch(void* const* d_in, const int* in_sizes, int n_in,
                              void* d_out, int out_size) {
    const float* x  = (const float*)d_in[0];
    const float* dw = (const float*)d_in[1];
    const float* ow = (const float*)d_in[2];
    const float* ob = (const float*)d_in[3];
    const float* w1 = (const float*)d_in[4];
    const float* b1 = (const float*)d_in[5];
    const float* w2 = (const float*)d_in[6];
    const float* b2 = (const float*)d_in[7];
    float* out = (float*)d_out;

    const int branch_smem = (4096 + 16896 + 4608) * 4;  // 102400 B
    cudaFuncSetAttribute(branch_kernel, cudaFuncAttributeMaxDynamicSharedMemorySize, branch_smem);

    transpose_kernel<<<dim3(512, 2, 4), dim3(32, 8)>>>(x);
    dwt_kernel<<<576, 256>>>(dw);
    offset_kernel<<<dim3(64, 4, 4), 256>>>(x, ow, ob);
    branch_kernel<<<dim3(64, 4, 4), 256, branch_smem>>>();
    se_kernel<<<1, 256>>>(w1, b1, w2, b2);
    final_kernel<<<4096, 256>>>(x, out);
}

// round 4
// speedup vs baseline: 1.5918x; 1.5918x over previous
#include <cuda_runtime.h>

#define HH 128
#define WW 128
#define HWN 16384
#define BHW (4 * 16384)
#define BN 4
#define CN 64

typedef unsigned long long ull;

__device__ __constant__ int c_RATES[4] = {2, 3, 5, 9};

// Scratch (static device globals: allocation-free, graph-capturable)
__device__ float g_xhwc[BN * HWN * CN];            // [b][p][c]
__device__ float g_off[4 * 18 * BHW];              // [j][k2][b*HW+p]  planar
__device__ float g_dwt[4 * 9 * 64 * 64];           // [i][k][c][o]
__device__ float g_cat[4 * BN * CN * HWN];         // [i][b][o][p]
__device__ float g_bsums[4 * BN * 128 * 64];       // [i][b][row][o]
__device__ float g_gate[BN * 256];                 // 1 + sigmoid(...)

__device__ __forceinline__ ull pack2(float a, float b) {
    ull r;
    asm("mov.b64 %0, {%1, %2};" : "=l"(r) : "f"(a), "f"(b));
    return r;
}
__device__ __forceinline__ void ffma2(ull& d, ull a, ull b) {
    asm("fma.rn.f32x2 %0, %1, %2, %0;" : "+l"(d) : "l"(a), "l"(b));
}

// ---------------- K1: NCHW -> NHWC transpose of x ----------------
__global__ void transpose_kernel(const float* __restrict__ x) {
    __shared__ float tile[32][33];
    int b  = blockIdx.z;
    int p0 = blockIdx.x * 32;
    int c0 = blockIdx.y * 32;
    for (int i = threadIdx.y; i < 32; i += 8)
        tile[i][threadIdx.x] = x[(b * 64 + c0 + i) * HWN + p0 + threadIdx.x];
    __syncthreads();
    for (int i = threadIdx.y; i < 32; i += 8)
        g_xhwc[(b * HWN + p0 + i) * 64 + c0 + threadIdx.x] = tile[threadIdx.x][i];
}

// ---------------- K1b: dw (i,o,c,3,3) -> g_dwt [i][k][c][o] ----------------
__global__ void dwt_kernel(const float* __restrict__ dw) {
    int idx = blockIdx.x * 256 + threadIdx.x;  // < 147456
    int i  = idx / 36864;
    int r  = idx % 36864;
    int k  = r / 4096;
    int r2 = r & 4095;
    int c  = r2 >> 6;
    int o  = r2 & 63;
    g_dwt[idx] = dw[((i * 64 + o) * 64 + c) * 9 + k];
}

// ---------------- K2: offset conv (64 -> 18, dilated 3x3, relu), f32x2 ----------------
// writes PLANAR layout: g_off[(j*18+k2)*BHW + b*HWN + p]
__global__ __launch_bounds__(256) void offset_kernel(const float* __restrict__ x,
                                                     const float* __restrict__ ow,
                                                     const float* __restrict__ ob) {
    __shared__ float ow_sh[9 * 64 * 20];
    int j = blockIdx.z, b = blockIdx.y;
    int rate = c_RATES[j];
    int tid = threadIdx.x;
    for (int idx = tid; idx < 9 * 64 * 20; idx += 256) {
        int k2 = idx % 20;
        int rest = idx / 20;
        int c = rest % 64;
        int t = rest / 64;
        ow_sh[idx] = (k2 < 18) ? ow[((j * 18 + k2) * 64 + c) * 9 + t] : 0.f;
    }
    __syncthreads();

    int p = blockIdx.x * 256 + tid;
    int y = p >> 7, xx = p & 127;
    ull acc2[10];
#pragma unroll
    for (int q = 0; q < 9; q++) acc2[q] = pack2(ob[j * 18 + 2 * q], ob[j * 18 + 2 * q + 1]);
    acc2[9] = 0ull;

    const float* xb = x + b * 64 * HWN;
    for (int t = 0; t < 9; t++) {
        int tyv = y + (t / 3 - 1) * rate;
        int txv = xx + (t % 3 - 1) * rate;
        if ((unsigned)tyv >= HH || (unsigned)txv >= WW) continue;
        const float* xp = xb + tyv * WW + txv;
#pragma unroll 4
        for (int c = 0; c < 64; c++) {
            float xc = xp[c * HWN];  // coalesced across warp
            ull xcc = pack2(xc, xc);
            const ull* wr = (const ull*)&ow_sh[(t * 64 + c) * 20];  // broadcast
#pragma unroll
            for (int q = 0; q < 10; q++) ffma2(acc2[q], wr[q], xcc);
        }
    }
    float* og = g_off + j * 18 * BHW + b * HWN + p;  // plane stride BHW, coalesced
#pragma unroll
    for (int q = 0; q < 9; q++) {
        float2 v = *(float2*)&acc2[q];
        og[(2 * q) * BHW]     = fmaxf(v.x, 0.f);
        og[(2 * q + 1) * BHW] = fmaxf(v.y, 0.f);
    }
}

// ---------------- K3: deform sample + GEMM per branch ----------------
// block = full image row (128 px) x 64 outputs, 128 threads, 8x8 tile, f32x2
#define SPITCH 132
__global__ __launch_bounds__(128, 4) void branch_kernel() {
    extern __shared__ float smem[];
    float* A_sh = smem;                  // 64*64   = 4096 floats
    float* S_sh = smem + 4096;           // 64*132  = 8448 floats

    int i = blockIdx.z, b = blockIdx.y, row = blockIdx.x;
    int p0 = row * 128;
    int j = (i + 3) & 3;
    int rate = c_RATES[i];
    int tid = threadIdx.x;
    int tx = tid & 15, ty = tid >> 4;
    int t3 = tid & 3;

    ull acc[8][4];
#pragma unroll
    for (int oy = 0; oy < 8; oy++)
#pragma unroll
        for (int q = 0; q < 4; q++) acc[oy][q] = 0ull;

    const float* xb   = &g_xhwc[b * HWN * 64];
    const float* dwt  = &g_dwt[i * 9 * 4096];
    const float* offb = g_off + j * 18 * BHW + b * HWN + p0;  // + k2*BHW + sp

    for (int k = 0; k < 9; k++) {
        __syncthreads();
        // stage A (dw k-chunk): 4096 floats
        {
            const float4* src = (const float4*)(dwt + k * 4096);
            float4* dst = (float4*)A_sh;
#pragma unroll
            for (int u = 0; u < 8; u++) dst[tid + u * 128] = src[tid + u * 128];
        }
        // stage S: bilinear gather, 32 pixels per pass (4 lanes/pixel), 4 passes
        int kyr = (k / 3 - 1) * rate;
        int kxr = (k % 3 - 1) * rate;
        const float* offY = offb + (2 * k) * BHW;
        const float* offX = offb + (2 * k + 1) * BHW;
#pragma unroll
        for (int pass = 0; pass < 4; pass++) {
            int sp = pass * 32 + (tid >> 2);
            float dy = __ldg(offY + sp);
            float dx = __ldg(offX + sp);
            float py = (float)(row + kyr) + dy;
            float px = (float)(sp + kxr) + dx;
            float fy = floorf(py), fx = floorf(px);
            int iy0 = (int)fy, ix0 = (int)fx;
            float wy1 = py - fy, wx1 = px - fx;
            float wy0 = 1.f - wy1, wx0 = 1.f - wx1;
            bool vy0 = (unsigned)iy0 < HH;
            bool vy1 = (unsigned)(iy0 + 1) < HH;
            bool vx0 = (unsigned)ix0 < WW;
            bool vx1 = (unsigned)(ix0 + 1) < WW;
            float w00 = (vy0 && vx0) ? wy0 * wx0 : 0.f;
            float w01 = (vy0 && vx1) ? wy0 * wx1 : 0.f;
            float w10 = (vy1 && vx0) ? wy1 * wx0 : 0.f;
            float w11 = (vy1 && vx1) ? wy1 * wx1 : 0.f;
            int cy0 = min(max(iy0, 0), HH - 1), cy1 = min(max(iy0 + 1, 0), HH - 1);
            int cx0 = min(max(ix0, 0), WW - 1), cx1 = min(max(ix0 + 1, 0), WW - 1);
            const float* b00 = xb + (cy0 * WW + cx0) * 64;
            const float* b01 = xb + (cy0 * WW + cx1) * 64;
            const float* b10 = xb + (cy1 * WW + cx0) * 64;
            const float* b11 = xb + (cy1 * WW + cx1) * 64;
#pragma unroll
            for (int u = 0; u < 4; u++) {
                int c0 = t3 * 4 + u * 16;   // interleaved channel groups (2-way STS)
                float4 a00 = *(const float4*)(b00 + c0);
                float4 a01 = *(const float4*)(b01 + c0);
                float4 a10 = *(const float4*)(b10 + c0);
                float4 a11 = *(const float4*)(b11 + c0);
                float4 s;
                s.x = w00 * a00.x + w01 * a01.x + w10 * a10.x + w11 * a11.x;
                s.y = w00 * a00.y + w01 * a01.y + w10 * a10.y + w11 * a11.y;
                s.z = w00 * a00.z + w01 * a01.z + w10 * a10.z + w11 * a11.z;
                s.w = w00 * a00.w + w01 * a01.w + w10 * a10.w + w11 * a11.w;
                float* dst = &S_sh[c0 * SPITCH + sp];
                dst[0]          = s.x;
                dst[SPITCH]     = s.y;
                dst[2 * SPITCH] = s.z;
                dst[3 * SPITCH] = s.w;
            }
        }
        __syncthreads();
        // GEMM: acc[oy][pp] += dup(A[c][ty*8+oy]) * S pixel-pairs
#pragma unroll 4
        for (int c = 0; c < 64; c++) {
            float4 a0 = *(const float4*)&A_sh[c * 64 + ty * 8];
            float4 a1 = *(const float4*)&A_sh[c * 64 + ty * 8 + 4];
            ulonglong2 B0 = *(const ulonglong2*)&S_sh[c * SPITCH + tx * 4];
            ulonglong2 B1 = *(const ulonglong2*)&S_sh[c * SPITCH + 64 + tx * 4];
            ull aa;
            aa = pack2(a0.x, a0.x); ffma2(acc[0][0], aa, B0.x); ffma2(acc[0][1], aa, B0.y); ffma2(acc[0][2], aa, B1.x); ffma2(acc[0][3], aa, B1.y);
            aa = pack2(a0.y, a0.y); ffma2(acc[1][0], aa, B0.x); ffma2(acc[1][1], aa, B0.y); ffma2(acc[1][2], aa, B1.x); ffma2(acc[1][3], aa, B1.y);
            aa = pack2(a0.z, a0.z); ffma2(acc[2][0], aa, B0.x); ffma2(acc[2][1], aa, B0.y); ffma2(acc[2][2], aa, B1.x); ffma2(acc[2][3], aa, B1.y);
            aa = pack2(a0.w, a0.w); ffma2(acc[3][0], aa, B0.x); ffma2(acc[3][1], aa, B0.y); ffma2(acc[3][2], aa, B1.x); ffma2(acc[3][3], aa, B1.y);
            aa = pack2(a1.x, a1.x); ffma2(acc[4][0], aa, B0.x); ffma2(acc[4][1], aa, B0.y); ffma2(acc[4][2], aa, B1.x); ffma2(acc[4][3], aa, B1.y);
            aa = pack2(a1.y, a1.y); ffma2(acc[5][0], aa, B0.x); ffma2(acc[5][1], aa, B0.y); ffma2(acc[5][2], aa, B1.x); ffma2(acc[5][3], aa, B1.y);
            aa = pack2(a1.z, a1.z); ffma2(acc[6][0], aa, B0.x); ffma2(acc[6][1], aa, B0.y); ffma2(acc[6][2], aa, B1.x); ffma2(acc[6][3], aa, B1.y);
            aa = pack2(a1.w, a1.w); ffma2(acc[7][0], aa, B0.x); ffma2(acc[7][1], aa, B0.y); ffma2(acc[7][2], aa, B1.x); ffma2(acc[7][3], aa, B1.y);
        }
    }

    // write outputs + per-row channel sums (deterministic)
    float* outp = &g_cat[((i * 4 + b) * 64) * HWN];
    float psum[8];
#pragma unroll
    for (int oy = 0; oy < 8; oy++) {
        int o = ty * 8 + oy;
        float2 p0v = *(float2*)&acc[oy][0];
        float2 p1v = *(float2*)&acc[oy][1];
        float2 p2v = *(float2*)&acc[oy][2];
        float2 p3v = *(float2*)&acc[oy][3];
        *(float4*)&outp[o * HWN + p0 + tx * 4]      = make_float4(p0v.x, p0v.y, p1v.x, p1v.y);
        *(float4*)&outp[o * HWN + p0 + 64 + tx * 4] = make_float4(p2v.x, p2v.y, p3v.x, p3v.y);
        psum[oy] = p0v.x + p0v.y + p1v.x + p1v.y + p2v.x + p2v.y + p3v.x + p3v.y;
    }
    __syncthreads();
    float* red = A_sh;  // reuse (GEMM done)
#pragma unroll
    for (int oy = 0; oy < 8; oy++) red[(ty * 8 + oy) * 16 + tx] = psum[oy];
    __syncthreads();
    if (tid < 64) {
        float s = 0.f;
#pragma unroll
        for (int t = 0; t < 16; t++) s += red[tid * 16 + t];
        g_bsums[((i * 4 + b) * 128 + row) * 64 + tid] = s;
    }
}

// ---------------- K4: SE MLP (tiny, one block) ----------------
__global__ void se_kernel(const float* __restrict__ w1, const float* __restrict__ b1,
                          const float* __restrict__ w2, const float* __restrict__ b2) {
    __shared__ float gm[4 * 256];
    __shared__ float h1[4 * 64];
    int tid = threadIdx.x;  // 256
    for (int idx = tid; idx < 1024; idx += 256) {
        int b = idx >> 8, ch = idx & 255;
        int i = ch >> 6, o = ch & 63;
        float s = 0.f;
        for (int r = 0; r < 128; r++)
            s += g_bsums[((i * 4 + b) * 128 + r) * 64 + o];
        gm[b * 256 + ch] = s * (1.f / 16384.f);
    }
    __syncthreads();
    {
        int b = tid >> 6, oc = tid & 63;
        float a = b1[oc];
        for (int ch = 0; ch < 256; ch++) a += w1[oc * 256 + ch] * gm[b * 256 + ch];
        h1[b * 64 + oc] = fmaxf(a, 0.f);
    }
    __syncthreads();
    for (int idx = tid; idx < 1024; idx += 256) {
        int b = idx >> 8, ch = idx & 255;
        float a = b2[ch];
        for (int oc = 0; oc < 64; oc++) a += w2[ch * 64 + oc] * h1[b * 64 + oc];
        g_gate[b * 256 + ch] = 1.f + 1.f / (1.f + expf(-a));
    }
}

// ---------------- K5: gated fuse + residual ----------------
__global__ void final_kernel(const float* __restrict__ x, float* __restrict__ out) {
    int idx = blockIdx.x * 256 + threadIdx.x;  // < 1048576 float4s
    int p4 = idx & 4095;
    int o  = (idx >> 12) & 63;
    int b  = idx >> 18;
    float4 a = ((const float4*)x)[idx];
#pragma unroll
    for (int i = 0; i < 4; i++) {
        float g = g_gate[b * 256 + i * 64 + o];
        float4 cv = ((const float4*)g_cat)[((i * 4 + b) * 64 + o) * 4096 + p4];
        a.x += g * cv.x;
        a.y += g * cv.y;
        a.z += g * cv.z;
        a.w += g * cv.w;
    }
    ((float4*)out)[idx] = a;
}

extern "C" void kernel_launch(void* const* d_in, const int* in_sizes, int n_in,
                              void* d_out, int out_size) {
    const float* x  = (const float*)d_in[0];
    const float* dw = (const float*)d_in[1];
    const float* ow = (const float*)d_in[2];
    const float* ob = (const float*)d_in[3];
    const float* w1 = (const float*)d_in[4];
    const float* b1 = (const float*)d_in[5];
    const float* w2 = (const float*)d_in[6];
    const float* b2 = (const float*)d_in[7];
    float* out = (float*)d_out;

    const int branch_smem = (4096 + 8448) * 4;  // 50176 B -> 4 blocks/SM
    cudaFuncSetAttribute(branch_kernel, cudaFuncAttributeMaxDynamicSharedMemorySize, branch_smem);

    transpose_kernel<<<dim3(512, 2, 4), dim3(32, 8)>>>(x);
    dwt_kernel<<<576, 256>>>(dw);
    offset_kernel<<<dim3(64, 4, 4), 256>>>(x, ow, ob);
    branch_kernel<<<dim3(128, 4, 4), 128, branch_smem>>>();
    se_kernel<<<1, 256>>>(w1, b1, w2, b2);
    final_kernel<<<4096, 256>>>(x, out);
}